// round 1
// baseline (speedup 1.0000x reference)
#include <cuda_runtime.h>
#include <math.h>

// Problem dims
#define BCH 4
#define CCH 256
#define HWT 4096          // H*W = 64*64
#define NTOK 16384        // B*HW

// ---------------- scratch (device globals; no allocations allowed) ------------
__device__ float g_hn[(size_t)NTOK * CCH];
__device__ float g_q [(size_t)NTOK * CCH];
__device__ float g_k [(size_t)NTOK * CCH];
__device__ float g_v [(size_t)NTOK * CCH];
__device__ float g_h [(size_t)NTOK * CCH];
__device__ float g_s [(size_t)BCH * HWT * HWT];   // 268 MB attention scores

// ---------------- packed f32x2 helpers (sm_103a dual-fp32 path) ---------------
__device__ __forceinline__ unsigned long long dup2(float a) {
    unsigned long long d;
    unsigned int ai = __float_as_uint(a);
    asm("mov.b64 %0, {%1, %1};" : "=l"(d) : "r"(ai));
    return d;
}
__device__ __forceinline__ void fma2(unsigned long long& d,
                                     unsigned long long a,
                                     unsigned long long b) {
    asm("fma.rn.f32x2 %0, %1, %2, %0;" : "+l"(d) : "l"(a), "l"(b));
}
__device__ __forceinline__ float2 unpack2(unsigned long long u) {
    float2 r;
    asm("mov.b64 {%0, %1}, %2;" : "=f"(r.x), "=f"(r.y) : "l"(u));
    return r;
}

// ---------------- GroupNorm (32 groups x 8ch, per pixel) ----------------------
// x: (B,C,H,W) -> g_hn: [token = b*4096+hw][c], normalized + affine
__global__ __launch_bounds__(256) void groupnorm_kernel(
    const float* __restrict__ x,
    const float* __restrict__ gnw,
    const float* __restrict__ gnb)
{
    __shared__ float tile[CCH][33];
    __shared__ float sw[CCH];
    __shared__ float sb[CCH];
    int tid = threadIdx.x;
    int b = blockIdx.x >> 7;                 // / 128 blocks per batch
    int hwbase = (blockIdx.x & 127) << 5;    // 32 tokens per block
    int tx = tid & 31, ty = tid >> 5;

    const float* xb = x + (size_t)b * CCH * HWT;
    for (int c = ty; c < CCH; c += 8)
        tile[c][tx] = xb[(size_t)c * HWT + hwbase + tx];
    sw[tid] = gnw[tid];
    sb[tid] = gnb[tid];
    __syncthreads();

    int tok = tx;
    #pragma unroll
    for (int gi = 0; gi < 4; gi++) {
        int g  = ty + gi * 8;
        int c0 = g * 8;
        float s = 0.f, ss = 0.f;
        #pragma unroll
        for (int j = 0; j < 8; j++) {
            float v = tile[c0 + j][tok];
            s += v; ss += v * v;
        }
        float m   = s * 0.125f;
        float var = ss * 0.125f - m * m;
        float r   = rsqrtf(var + 1e-6f);
        #pragma unroll
        for (int j = 0; j < 8; j++) {
            int c = c0 + j;
            tile[c][tok] = (tile[c][tok] - m) * r * sw[c] + sb[c];
        }
    }
    __syncthreads();

    float* outp = g_hn + (size_t)(b * HWT + hwbase) * CCH;
    for (int it = 0; it < 32; it++)
        outp[(size_t)it * CCH + tid] = tile[tid][it];
}

// ---------------- generic fp32 GEMM (f32x2 inner loop) ------------------------
// C[M,N] = alpha * (A[M,K] * B + bias)   (+x residual, transposed layout, EPI=1)
// TRANSB: B is [N,K] row-major (NT, used for Q*K^T). else B is [K,N] row-major.
// Tiles: 128x128x32, 256 threads, 8x8 per-thread tile. All dims divide evenly.
template <bool TRANSB, int EPI>
__global__ __launch_bounds__(256) void gemm_kernel(
    const float* __restrict__ A,
    const float* __restrict__ Bm,
    float* __restrict__ C,
    const float* __restrict__ bias,
    const float* __restrict__ xres,
    float alpha,
    int M, int N, int K,
    long long strA, long long strB, long long strC)
{
    __shared__ float As[32][132];
    __shared__ float Bs[32][132];

    int tid = threadIdx.x;
    int bn = blockIdx.x, bmv = blockIdx.y, bz = blockIdx.z;
    const float* Ap = A + (long long)bz * strA + (long long)bmv * 128 * K;
    const float* Bp = Bm + (long long)bz * strB;
    int nBase = bn * 128;
    int tx = tid & 15, ty = tid >> 4;

    unsigned long long acc[8][4];
    #pragma unroll
    for (int r = 0; r < 8; r++)
        #pragma unroll
        for (int j = 0; j < 4; j++) acc[r][j] = 0ull;

    for (int kt = 0; kt < K; kt += 32) {
        // Load A tile [128 x 32], transposed into As[k][m]
        #pragma unroll
        for (int i = 0; i < 4; i++) {
            int v = tid + i * 256;
            int m = v >> 3, kq = (v & 7) << 2;
            float4 av = *(const float4*)(Ap + (long long)m * K + kt + kq);
            As[kq + 0][m] = av.x; As[kq + 1][m] = av.y;
            As[kq + 2][m] = av.z; As[kq + 3][m] = av.w;
        }
        if (TRANSB) {
            // B is [N,K]: same transposing loader
            #pragma unroll
            for (int i = 0; i < 4; i++) {
                int v = tid + i * 256;
                int n = v >> 3, kq = (v & 7) << 2;
                float4 bv = *(const float4*)(Bp + (long long)(nBase + n) * K + kt + kq);
                Bs[kq + 0][n] = bv.x; Bs[kq + 1][n] = bv.y;
                Bs[kq + 2][n] = bv.z; Bs[kq + 3][n] = bv.w;
            }
        } else {
            // B is [K,N]: direct
            #pragma unroll
            for (int i = 0; i < 4; i++) {
                int v = tid + i * 256;
                int kk = v >> 5, n4 = (v & 31) << 2;
                float4 bv = *(const float4*)(Bp + (long long)(kt + kk) * N + nBase + n4);
                *(float4*)&Bs[kk][n4] = bv;
            }
        }
        __syncthreads();

        #pragma unroll
        for (int k = 0; k < 32; k++) {
            float4 a0 = *(const float4*)&As[k][ty * 4];
            float4 a1 = *(const float4*)&As[k][ty * 4 + 64];
            ulonglong2 bb0 = *(const ulonglong2*)&Bs[k][tx * 4];
            ulonglong2 bb1 = *(const ulonglong2*)&Bs[k][tx * 4 + 64];
            unsigned long long ad[8];
            ad[0] = dup2(a0.x); ad[1] = dup2(a0.y);
            ad[2] = dup2(a0.z); ad[3] = dup2(a0.w);
            ad[4] = dup2(a1.x); ad[5] = dup2(a1.y);
            ad[6] = dup2(a1.z); ad[7] = dup2(a1.w);
            #pragma unroll
            for (int r = 0; r < 8; r++) {
                fma2(acc[r][0], ad[r], bb0.x);
                fma2(acc[r][1], ad[r], bb0.y);
                fma2(acc[r][2], ad[r], bb1.x);
                fma2(acc[r][3], ad[r], bb1.y);
            }
        }
        __syncthreads();
    }

    // epilogue
    int nc0 = nBase + tx * 4;
    float bb[8];
    #pragma unroll
    for (int e = 0; e < 8; e++) {
        int ncol = nc0 + (e & 3) + ((e >> 2) << 6);
        bb[e] = bias ? bias[ncol] : 0.f;
    }
    #pragma unroll
    for (int r = 0; r < 8; r++) {
        int m = bmv * 128 + ty * 4 + (r & 3) + ((r >> 2) << 6);
        float2 f0 = unpack2(acc[r][0]);
        float2 f1 = unpack2(acc[r][1]);
        float2 f2 = unpack2(acc[r][2]);
        float2 f3 = unpack2(acc[r][3]);
        float o[8] = {f0.x, f0.y, f1.x, f1.y, f2.x, f2.y, f3.x, f3.y};
        if (EPI == 0) {
            float* Cr = C + (long long)bz * strC + (long long)m * N;
            float4 s0 = make_float4(alpha * (o[0] + bb[0]), alpha * (o[1] + bb[1]),
                                    alpha * (o[2] + bb[2]), alpha * (o[3] + bb[3]));
            float4 s1 = make_float4(alpha * (o[4] + bb[4]), alpha * (o[5] + bb[5]),
                                    alpha * (o[6] + bb[6]), alpha * (o[7] + bb[7]));
            *(float4*)(Cr + nc0)      = s0;
            *(float4*)(Cr + nc0 + 64) = s1;
        } else {
            // out[(b*256 + n)*4096 + hw] = x[...] + val + bias[n]
            int bidx = m >> 12, hw = m & 4095;
            long long obase = ((long long)bidx << 20) + hw;
            #pragma unroll
            for (int e = 0; e < 8; e++) {
                int ncol = nc0 + (e & 3) + ((e >> 2) << 6);
                long long idx = obase + ((long long)ncol << 12);
                C[idx] = xres[idx] + o[e] + bb[e];
            }
        }
    }
}

// ---------------- masked softmax over 4096 keys per row -----------------------
// mask: key col (j % 64) must be <= query col (row % 64). In-place on g_s.
__global__ __launch_bounds__(256) void softmax_kernel() {
    int row = blockIdx.x;
    int wq = row & 63;
    float* S = g_s + (size_t)row * HWT;
    int tid = threadIdx.x;
    __shared__ float red[8];

    float vals[16];
    float mx = -INFINITY;
    #pragma unroll
    for (int it = 0; it < 16; it++) {
        int j = it * 256 + tid;
        float v = ((j & 63) <= wq) ? S[j] : -INFINITY;
        vals[it] = v;
        mx = fmaxf(mx, v);
    }
    #pragma unroll
    for (int o = 16; o > 0; o >>= 1)
        mx = fmaxf(mx, __shfl_xor_sync(0xffffffffu, mx, o));
    if ((tid & 31) == 0) red[tid >> 5] = mx;
    __syncthreads();
    mx = red[0];
    #pragma unroll
    for (int i = 1; i < 8; i++) mx = fmaxf(mx, red[i]);
    __syncthreads();

    float sum = 0.f;
    #pragma unroll
    for (int it = 0; it < 16; it++) {
        float e = __expf(vals[it] - mx);
        vals[it] = e;
        sum += e;
    }
    #pragma unroll
    for (int o = 16; o > 0; o >>= 1)
        sum += __shfl_xor_sync(0xffffffffu, sum, o);
    if ((tid & 31) == 0) red[tid >> 5] = sum;
    __syncthreads();
    sum = 0.f;
    #pragma unroll
    for (int i = 0; i < 8; i++) sum += red[i];

    float inv = 1.f / sum;
    #pragma unroll
    for (int it = 0; it < 16; it++)
        S[it * 256 + tid] = vals[it] * inv;
}

// ---------------- launch ------------------------------------------------------
extern "C" void kernel_launch(void* const* d_in, const int* in_sizes, int n_in,
                              void* d_out, int out_size) {
    (void)in_sizes; (void)n_in; (void)out_size;
    const float* x   = (const float*)d_in[0];
    const float* gnw = (const float*)d_in[1];
    const float* gnb = (const float*)d_in[2];
    const float* w0  = (const float*)d_in[3];
    const float* b0  = (const float*)d_in[4];
    const float* w1  = (const float*)d_in[5];
    const float* b1  = (const float*)d_in[6];
    const float* w2  = (const float*)d_in[7];
    const float* b2  = (const float*)d_in[8];
    const float* w3  = (const float*)d_in[9];
    const float* b3  = (const float*)d_in[10];
    float* out = (float*)d_out;

    void *phn, *pq, *pk, *pv, *ph, *ps;
    cudaGetSymbolAddress(&phn, g_hn);
    cudaGetSymbolAddress(&pq,  g_q);
    cudaGetSymbolAddress(&pk,  g_k);
    cudaGetSymbolAddress(&pv,  g_v);
    cudaGetSymbolAddress(&ph,  g_h);
    cudaGetSymbolAddress(&ps,  g_s);
    float* hn = (float*)phn;
    float* q  = (float*)pq;
    float* k  = (float*)pk;
    float* v  = (float*)pv;
    float* h  = (float*)ph;
    float* s  = (float*)ps;

    const long long QKV_STR = (long long)HWT * CCH;      // 1,048,576
    const long long S_STR   = (long long)HWT * HWT;      // 16,777,216

    // 1. GroupNorm
    groupnorm_kernel<<<512, 256>>>(x, gnw, gnb);

    // 2. Q,K,V projections (Q pre-scaled by C^-0.5 = 1/16)
    dim3 gq(2, 128, 1);
    gemm_kernel<false, 0><<<gq, 256>>>(hn, w0, q, b0, nullptr, 0.0625f,
                                       NTOK, CCH, CCH, 0, 0, 0);
    gemm_kernel<false, 0><<<gq, 256>>>(hn, w1, k, b1, nullptr, 1.0f,
                                       NTOK, CCH, CCH, 0, 0, 0);
    gemm_kernel<false, 0><<<gq, 256>>>(hn, w2, v, b2, nullptr, 1.0f,
                                       NTOK, CCH, CCH, 0, 0, 0);

    // 3. Scores S = Q * K^T (batched NT)
    dim3 gs(32, 32, 4);
    gemm_kernel<true, 0><<<gs, 256>>>(q, k, s, nullptr, nullptr, 1.0f,
                                      HWT, HWT, CCH, QKV_STR, QKV_STR, S_STR);

    // 4. Masked softmax (in place)
    softmax_kernel<<<NTOK, 256>>>();

    // 5. H = P * V (batched NN)
    dim3 gp(2, 32, 4);
    gemm_kernel<false, 0><<<gp, 256>>>(s, v, h, nullptr, nullptr, 1.0f,
                                       HWT, CCH, HWT, S_STR, QKV_STR, QKV_STR);

    // 6. out = x + H*w3 + b3 (transposed store back to BCHW)
    dim3 gf(2, 128, 1);
    gemm_kernel<false, 1><<<gf, 256>>>(h, w3, out, b3, x, 1.0f,
                                       NTOK, CCH, CCH, 0, 0, 0);
}

// round 4
// speedup vs baseline: 1.6566x; 1.6566x over previous
#include <cuda_runtime.h>
#include <math.h>
#include <stdint.h>

// Problem dims
#define BCH 4
#define CCH 256
#define HWT 4096          // H*W = 64*64
#define NTOK 16384        // B*HW

// ---------------- scratch (device globals; no allocations allowed) ------------
// Token order inside each batch is PERMUTED: p = w*64 + h (transpose of spatial).
// This makes the causal mask (key col j > query col w) block-lower-triangular
// with 64-token blocks, diagonal block fully allowed.
__device__ float g_hn[(size_t)NTOK * CCH];
__device__ float g_q [(size_t)NTOK * CCH];
__device__ float g_k [(size_t)NTOK * CCH];
__device__ float g_vt[(size_t)NTOK * CCH];   // V^T per batch: [b][c][p]
__device__ float g_h [(size_t)NTOK * CCH];
__device__ float g_s [(size_t)BCH * HWT * HWT];   // 268 MB attention scores

// ---------------- helpers -----------------------------------------------------
__device__ __forceinline__ uint32_t smem_u32(const void* p) {
    uint32_t a;
    asm("{ .reg .u64 t; cvta.to.shared.u64 t, %1; cvt.u32.u64 %0, t; }"
        : "=r"(a) : "l"(p));
    return a;
}
__device__ __forceinline__ uint32_t tf32_rna(float x) {
    uint32_t u;
    asm("cvt.rna.tf32.f32 %0, %1;" : "=r"(u) : "f"(x));
    return u;
}
__device__ __forceinline__ void cpa16(uint32_t dst, const void* src) {
    asm volatile("cp.async.cg.shared.global [%0], [%1], 16;"
                 :: "r"(dst), "l"(src));
}
__device__ __forceinline__ void cpa_commit() {
    asm volatile("cp.async.commit_group;" ::: "memory");
}
__device__ __forceinline__ void cpa_wait1() {
    asm volatile("cp.async.wait_group 1;" ::: "memory");
}
// m16n8k8 tf32 MMA (sm_80+ path, works on plain sm_103 target)
__device__ __forceinline__ void mma8(float* c, const uint32_t* a, const uint32_t* b) {
    asm volatile("mma.sync.aligned.m16n8k8.row.col.f32.tf32.tf32.f32 "
        "{%0,%1,%2,%3}, {%4,%5,%6,%7}, {%8,%9}, {%0,%1,%2,%3};"
        : "+f"(c[0]), "+f"(c[1]), "+f"(c[2]), "+f"(c[3])
        : "r"(a[0]), "r"(a[1]), "r"(a[2]), "r"(a[3]), "r"(b[0]), "r"(b[1]));
}
// f32x2 packed helpers for SIMT GEMM
__device__ __forceinline__ unsigned long long dup2(float a) {
    unsigned long long d;
    unsigned int ai = __float_as_uint(a);
    asm("mov.b64 %0, {%1, %1};" : "=l"(d) : "r"(ai));
    return d;
}
__device__ __forceinline__ void fma2(unsigned long long& d,
                                     unsigned long long a,
                                     unsigned long long b) {
    asm("fma.rn.f32x2 %0, %1, %2, %0;" : "+l"(d) : "l"(a), "l"(b));
}
__device__ __forceinline__ float2 unpack2(unsigned long long u) {
    float2 r;
    asm("mov.b64 {%0, %1}, %2;" : "=f"(r.x), "=f"(r.y) : "l"(u));
    return r;
}

// ---------------- GroupNorm (32 groups x 8ch, per pixel) ----------------------
// x: (B,C,H,W) -> g_hn in PERMUTED token order p = w*64 + h.
__global__ __launch_bounds__(256) void groupnorm_kernel(
    const float* __restrict__ x,
    const float* __restrict__ gnw,
    const float* __restrict__ gnb)
{
    __shared__ float tile[CCH][33];
    __shared__ float sw[CCH];
    __shared__ float sb[CCH];
    int tid = threadIdx.x;
    int b = blockIdx.x >> 7;
    int hwbase = (blockIdx.x & 127) << 5;    // 32 consecutive spatial s
    int tx = tid & 31, ty = tid >> 5;

    const float* xb = x + (size_t)b * CCH * HWT;
    for (int c = ty; c < CCH; c += 8)
        tile[c][tx] = xb[(size_t)c * HWT + hwbase + tx];
    sw[tid] = gnw[tid];
    sb[tid] = gnb[tid];
    __syncthreads();

    int tok = tx;
    #pragma unroll
    for (int gi = 0; gi < 4; gi++) {
        int g  = ty + gi * 8;
        int c0 = g * 8;
        float s = 0.f, ss = 0.f;
        #pragma unroll
        for (int j = 0; j < 8; j++) {
            float v = tile[c0 + j][tok];
            s += v; ss += v * v;
        }
        float m   = s * 0.125f;
        float var = ss * 0.125f - m * m;
        float r   = rsqrtf(var + 1e-6f);
        #pragma unroll
        for (int j = 0; j < 8; j++) {
            int c = c0 + j;
            tile[c][tok] = (tile[c][tok] - m) * r * sw[c] + sb[c];
        }
    }
    __syncthreads();

    // permuted write: s = hwbase+it (same h for all it), p = w*64 + h
    int h = hwbase >> 6;
    float* outb = g_hn + ((size_t)b << 12) * CCH;
    for (int it = 0; it < 32; it++) {
        int w = (hwbase + it) & 63;
        int p = (w << 6) | h;
        outb[(size_t)p * CCH + tid] = tile[tid][it];
    }
}

// ---------------- SIMT fp32 GEMM (f32x2) for N=K=256 projections --------------
// EPI=0: C[m][n] = alpha*(val + bias)
// EPI=1: out[(b*256+n)*4096 + s] = x[...] + val + bias   (A rows PERM-indexed)
// EPI=2: vt[(b*256+n)*4096 + p]  = val + bias            (V transposed)
template <int EPI, bool PERM>
__global__ __launch_bounds__(256) void gemm_kernel(
    const float* __restrict__ A,
    const float* __restrict__ Bm,
    float* __restrict__ C,
    const float* __restrict__ bias,
    const float* __restrict__ xres,
    float alpha,
    int M, int N, int K)
{
    __shared__ float As[32][132];
    __shared__ float Bs[32][132];

    int tid = threadIdx.x;
    int bn = blockIdx.x, bmv = blockIdx.y;
    int nBase = bn * 128;
    int tx = tid & 15, ty = tid >> 4;

    unsigned long long acc[8][4];
    #pragma unroll
    for (int r = 0; r < 8; r++)
        #pragma unroll
        for (int j = 0; j < 4; j++) acc[r][j] = 0ull;

    for (int kt = 0; kt < K; kt += 32) {
        #pragma unroll
        for (int i = 0; i < 4; i++) {
            int v = tid + i * 256;
            int m = v >> 3, kq = (v & 7) << 2;
            long long arow;
            int gr = bmv * 128 + m;
            if (PERM) {
                int t = gr & 4095;
                arow = (long long)((gr & ~4095) | ((t & 63) << 6) | (t >> 6));
            } else {
                arow = (long long)gr;
            }
            float4 av = *(const float4*)(A + arow * K + kt + kq);
            As[kq + 0][m] = av.x; As[kq + 1][m] = av.y;
            As[kq + 2][m] = av.z; As[kq + 3][m] = av.w;
        }
        #pragma unroll
        for (int i = 0; i < 4; i++) {
            int v = tid + i * 256;
            int kk = v >> 5, n4 = (v & 31) << 2;
            float4 bv = *(const float4*)(Bm + (long long)(kt + kk) * N + nBase + n4);
            *(float4*)&Bs[kk][n4] = bv;
        }
        __syncthreads();

        #pragma unroll
        for (int k = 0; k < 32; k++) {
            float4 a0 = *(const float4*)&As[k][ty * 4];
            float4 a1 = *(const float4*)&As[k][ty * 4 + 64];
            ulonglong2 bb0 = *(const ulonglong2*)&Bs[k][tx * 4];
            ulonglong2 bb1 = *(const ulonglong2*)&Bs[k][tx * 4 + 64];
            unsigned long long ad[8];
            ad[0] = dup2(a0.x); ad[1] = dup2(a0.y);
            ad[2] = dup2(a0.z); ad[3] = dup2(a0.w);
            ad[4] = dup2(a1.x); ad[5] = dup2(a1.y);
            ad[6] = dup2(a1.z); ad[7] = dup2(a1.w);
            #pragma unroll
            for (int r = 0; r < 8; r++) {
                fma2(acc[r][0], ad[r], bb0.x);
                fma2(acc[r][1], ad[r], bb0.y);
                fma2(acc[r][2], ad[r], bb1.x);
                fma2(acc[r][3], ad[r], bb1.y);
            }
        }
        __syncthreads();
    }

    int nc0 = nBase + tx * 4;
    float bb[8];
    #pragma unroll
    for (int e = 0; e < 8; e++) {
        int ncol = nc0 + (e & 3) + ((e >> 2) << 6);
        bb[e] = bias ? bias[ncol] : 0.f;
    }
    #pragma unroll
    for (int r = 0; r < 8; r++) {
        int m = bmv * 128 + ty * 4 + (r & 3) + ((r >> 2) << 6);
        float2 f0 = unpack2(acc[r][0]);
        float2 f1 = unpack2(acc[r][1]);
        float2 f2 = unpack2(acc[r][2]);
        float2 f3 = unpack2(acc[r][3]);
        float o[8] = {f0.x, f0.y, f1.x, f1.y, f2.x, f2.y, f3.x, f3.y};
        if (EPI == 0) {
            float* Cr = C + (long long)m * N;
            *(float4*)(Cr + nc0) = make_float4(
                alpha * (o[0] + bb[0]), alpha * (o[1] + bb[1]),
                alpha * (o[2] + bb[2]), alpha * (o[3] + bb[3]));
            *(float4*)(Cr + nc0 + 64) = make_float4(
                alpha * (o[4] + bb[4]), alpha * (o[5] + bb[5]),
                alpha * (o[6] + bb[6]), alpha * (o[7] + bb[7]));
        } else if (EPI == 2) {
            int bidx = m >> 12, tokp = m & 4095;
            long long obase = ((long long)bidx << 20) + tokp;
            #pragma unroll
            for (int e = 0; e < 8; e++) {
                int ncol = nc0 + (e & 3) + ((e >> 2) << 6);
                C[obase + ((long long)ncol << 12)] = o[e] + bb[e];
            }
        } else {  // EPI == 1: m is in s-order (A rows were PERM-fetched)
            int bidx = m >> 12, sidx = m & 4095;
            long long obase = ((long long)bidx << 20) + sidx;
            #pragma unroll
            for (int e = 0; e < 8; e++) {
                int ncol = nc0 + (e & 3) + ((e >> 2) << 6);
                long long idx = obase + ((long long)ncol << 12);
                C[idx] = xres[idx] + o[e] + bb[e];
            }
        }
    }
}

// ---------------- tensor-core NT GEMM via mma.sync tf32 -----------------------
// C[128 x 128] tiles. A [M x K] row-major, B [N x K] row-major (NT).
// SPLIT3: 3xTF32 hi/lo emulation (near-fp32). TRI: only nt <= mt tiles (scores).
// !TRI (PV): mt processed descending, K_tile = 128*(mt+1) (block-causal K range).
// 8 warps (2m x 4n), warp tile 64x32, m16n8k8 micro-tiles.
template <bool SPLIT3, bool TRI>
__global__ __launch_bounds__(256) void mma_nt_kernel(
    const float* __restrict__ A, const float* __restrict__ B, float* __restrict__ C,
    int lda, int ldb, int ldc, int Kfull,
    long long strA, long long strB, long long strC)
{
    int nt = blockIdx.x, bz = blockIdx.z;
    int mt;
    if (TRI) {
        mt = blockIdx.y;
        if (nt > mt) return;
    } else {
        mt = (int)gridDim.y - 1 - (int)blockIdx.y;   // longest first
    }
    int Ktile = TRI ? Kfull : 128 * (mt + 1);

    extern __shared__ float sm[];
    uint32_t sbase = smem_u32(sm);

    int tid = threadIdx.x;
    int lane = tid & 31, wid = tid >> 5;
    int wm = (wid >> 2) * 64, wn = (wid & 3) * 32;
    int gid = lane >> 2, tg = lane & 3;

    const float* Ap = A + (long long)bz * strA + (long long)mt * 128 * lda;
    const float* Bp = B + (long long)bz * strB + (long long)nt * 128 * ldb;

    int lrow = tid >> 1;             // 0..127
    int lcol0 = (tid & 1) * 16;      // 0 or 16

    float acc[4][4][4];
    #pragma unroll
    for (int mi = 0; mi < 4; mi++)
        #pragma unroll
        for (int ni = 0; ni < 4; ni++)
            #pragma unroll
            for (int e = 0; e < 4; e++) acc[mi][ni][e] = 0.f;

    // smem layout: A buffers [2][128][36] then B buffers [2][128][36] floats
    // byte offsets: A buf p at p*18432; B buf p at 36864 + p*18432
    uint32_t a_s0 = sbase + (uint32_t)lrow * 144u + (uint32_t)lcol0 * 4u;
    const int NC = Ktile >> 5;

    {   // prologue
        const float* ag = Ap + (long long)lrow * lda + lcol0;
        const float* bg = Bp + (long long)lrow * ldb + lcol0;
        #pragma unroll
        for (int i = 0; i < 4; i++) {
            cpa16(a_s0 + i * 16u, ag + i * 4);
            cpa16(a_s0 + 36864u + i * 16u, bg + i * 4);
        }
        cpa_commit();
        if (NC > 1) {
            #pragma unroll
            for (int i = 0; i < 4; i++) {
                cpa16(a_s0 + 18432u + i * 16u, ag + 32 + i * 4);
                cpa16(a_s0 + 18432u + 36864u + i * 16u, bg + 32 + i * 4);
            }
        }
        cpa_commit();
    }

    for (int c = 0; c < NC; c++) {
        cpa_wait1();
        __syncthreads();
        int p = c & 1;
        const float* Ab = sm + p * 4608;
        const float* Bb = sm + 9216 + p * 4608;

        #pragma unroll
        for (int kk = 0; kk < 32; kk += 8) {
            uint32_t ahi[4][4], alo[4][4];
            #pragma unroll
            for (int mi = 0; mi < 4; mi++) {
                int r = wm + mi * 16 + gid;
                float a0 = Ab[r * 36 + kk + tg];
                float a1 = Ab[(r + 8) * 36 + kk + tg];
                float a2 = Ab[r * 36 + kk + tg + 4];
                float a3 = Ab[(r + 8) * 36 + kk + tg + 4];
                ahi[mi][0] = tf32_rna(a0);
                ahi[mi][1] = tf32_rna(a1);
                ahi[mi][2] = tf32_rna(a2);
                ahi[mi][3] = tf32_rna(a3);
                if (SPLIT3) {
                    alo[mi][0] = tf32_rna(a0 - __uint_as_float(ahi[mi][0]));
                    alo[mi][1] = tf32_rna(a1 - __uint_as_float(ahi[mi][1]));
                    alo[mi][2] = tf32_rna(a2 - __uint_as_float(ahi[mi][2]));
                    alo[mi][3] = tf32_rna(a3 - __uint_as_float(ahi[mi][3]));
                }
            }
            #pragma unroll
            for (int ni = 0; ni < 4; ni++) {
                int rn = wn + ni * 8 + gid;
                float b0 = Bb[rn * 36 + kk + tg];
                float b1 = Bb[rn * 36 + kk + tg + 4];
                uint32_t bhi[2], blo[2];
                bhi[0] = tf32_rna(b0);
                bhi[1] = tf32_rna(b1);
                if (SPLIT3) {
                    blo[0] = tf32_rna(b0 - __uint_as_float(bhi[0]));
                    blo[1] = tf32_rna(b1 - __uint_as_float(bhi[1]));
                }
                #pragma unroll
                for (int mi = 0; mi < 4; mi++) {
                    mma8(acc[mi][ni], ahi[mi], bhi);
                    if (SPLIT3) {
                        mma8(acc[mi][ni], alo[mi], bhi);
                        mma8(acc[mi][ni], ahi[mi], blo);
                    }
                }
            }
        }
        __syncthreads();
        if (c + 2 < NC) {
            int kt = (c + 2) * 32;
            const float* ag = Ap + (long long)lrow * lda + kt + lcol0;
            const float* bg = Bp + (long long)lrow * ldb + kt + lcol0;
            uint32_t dsta = a_s0 + (uint32_t)p * 18432u;
            #pragma unroll
            for (int i = 0; i < 4; i++) {
                cpa16(dsta + i * 16u, ag + i * 4);
                cpa16(dsta + 36864u + i * 16u, bg + i * 4);
            }
        }
        cpa_commit();
    }

    float* Cp = C + (long long)bz * strC + (long long)(mt * 128) * ldc + nt * 128;
    #pragma unroll
    for (int mi = 0; mi < 4; mi++) {
        int r = wm + mi * 16 + gid;
        #pragma unroll
        for (int ni = 0; ni < 4; ni++) {
            int col = wn + ni * 8 + tg * 2;
            *(float2*)(Cp + (long long)r * ldc + col) =
                make_float2(acc[mi][ni][0], acc[mi][ni][1]);
            *(float2*)(Cp + (long long)(r + 8) * ldc + col) =
                make_float2(acc[mi][ni][2], acc[mi][ni][3]);
        }
    }
}

// ---------------- masked softmax, variable length L = (wq+1)*64 ---------------
__global__ __launch_bounds__(256) void softmax_kernel() {
    int row = blockIdx.x;
    int p = row & 4095;
    int wq = p >> 6;
    int L = (wq + 1) << 6;
    float* S = g_s + (size_t)row * HWT;
    int tid = threadIdx.x;
    __shared__ float red[8];

    float mx = -1e30f;
    for (int j = tid; j < L; j += 256) mx = fmaxf(mx, S[j]);
    #pragma unroll
    for (int o = 16; o > 0; o >>= 1)
        mx = fmaxf(mx, __shfl_xor_sync(0xffffffffu, mx, o));
    if ((tid & 31) == 0) red[tid >> 5] = mx;
    __syncthreads();
    mx = red[0];
    #pragma unroll
    for (int i = 1; i < 8; i++) mx = fmaxf(mx, red[i]);
    __syncthreads();

    float sum = 0.f;
    for (int j = tid; j < L; j += 256) sum += __expf(S[j] - mx);
    #pragma unroll
    for (int o = 16; o > 0; o >>= 1)
        sum += __shfl_xor_sync(0xffffffffu, sum, o);
    if ((tid & 31) == 0) red[tid >> 5] = sum;
    __syncthreads();
    sum = 0.f;
    #pragma unroll
    for (int i = 0; i < 8; i++) sum += red[i];

    float inv = 1.f / sum;
    for (int j = tid; j < L; j += 256) S[j] = __expf(S[j] - mx) * inv;
    // zero-fill pad keys up to the 128-tile boundary so PV needs no masking
    if (!(wq & 1) && tid < 64) S[L + tid] = 0.f;
}

// ---------------- launch ------------------------------------------------------
extern "C" void kernel_launch(void* const* d_in, const int* in_sizes, int n_in,
                              void* d_out, int out_size) {
    (void)in_sizes; (void)n_in; (void)out_size;
    const float* x   = (const float*)d_in[0];
    const float* gnw = (const float*)d_in[1];
    const float* gnb = (const float*)d_in[2];
    const float* w0  = (const float*)d_in[3];
    const float* b0  = (const float*)d_in[4];
    const float* w1  = (const float*)d_in[5];
    const float* b1  = (const float*)d_in[6];
    const float* w2  = (const float*)d_in[7];
    const float* b2  = (const float*)d_in[8];
    const float* w3  = (const float*)d_in[9];
    const float* b3  = (const float*)d_in[10];
    float* out = (float*)d_out;

    const int MMA_SMEM = 73728;
    cudaFuncSetAttribute(mma_nt_kernel<true, true>,
                         cudaFuncAttributeMaxDynamicSharedMemorySize, MMA_SMEM);
    cudaFuncSetAttribute(mma_nt_kernel<false, false>,
                         cudaFuncAttributeMaxDynamicSharedMemorySize, MMA_SMEM);

    void *phn, *pq, *pk, *pvt, *ph, *ps;
    cudaGetSymbolAddress(&phn, g_hn);
    cudaGetSymbolAddress(&pq,  g_q);
    cudaGetSymbolAddress(&pk,  g_k);
    cudaGetSymbolAddress(&pvt, g_vt);
    cudaGetSymbolAddress(&ph,  g_h);
    cudaGetSymbolAddress(&ps,  g_s);
    float* hn = (float*)phn;
    float* q  = (float*)pq;
    float* k  = (float*)pk;
    float* vt = (float*)pvt;
    float* h  = (float*)ph;
    float* s  = (float*)ps;

    const long long QKV_STR = (long long)HWT * CCH;      // 1,048,576
    const long long S_STR   = (long long)HWT * HWT;      // 16,777,216

    // 1. GroupNorm (writes permuted token order)
    groupnorm_kernel<<<512, 256>>>(x, gnw, gnb);

    // 2. Q,K,V projections (SIMT fp32; Q pre-scaled by C^-0.5 = 1/16)
    dim3 gq(2, 128, 1);
    gemm_kernel<0, false><<<gq, 256>>>(hn, w0, q, b0, nullptr, 0.0625f, NTOK, CCH, CCH);
    gemm_kernel<0, false><<<gq, 256>>>(hn, w1, k, b1, nullptr, 1.0f,    NTOK, CCH, CCH);
    gemm_kernel<2, false><<<gq, 256>>>(hn, w2, vt, b2, nullptr, 1.0f,   NTOK, CCH, CCH);

    // 3. Scores S = Q*K^T, tensor cores, 3xTF32, triangular tiles only
    dim3 gs(32, 32, 4);
    mma_nt_kernel<true, true><<<gs, 256, MMA_SMEM>>>(
        q, k, s, CCH, CCH, HWT, CCH, QKV_STR, QKV_STR, S_STR);

    // 4. Masked softmax (variable length + pad zero-fill)
    softmax_kernel<<<NTOK, 256>>>();

    // 5. H = P * V^T, tensor cores, tf32, causal K range per tile
    dim3 gp(2, 32, 4);
    mma_nt_kernel<false, false><<<gp, 256, MMA_SMEM>>>(
        s, vt, h, HWT, HWT, CCH, 0, S_STR, QKV_STR, QKV_STR);

    // 6. out = x + H*w3 + b3 (A rows un-permuted via PERM fetch)
    dim3 gf(2, 128, 1);
    gemm_kernel<1, true><<<gf, 256>>>(h, w3, out, b3, x, 1.0f, NTOK, CCH, CCH);
}